// round 4
// baseline (speedup 1.0000x reference)
#include <cuda_runtime.h>
#include <cuda_bf16.h>
#include <cstdint>

// ---------------------------------------------------------------------------
// Problem constants
// ---------------------------------------------------------------------------
#define B_  256
#define T_  512
#define I_  300
#define H_  64
#define G3  192          // 3*H
#define NCAT 384         // 6*H
#define KP  320          // K padded (10 tiles of 32)
#define M_  (B_ * T_)    // 131072

#define BM 128
#define BN 128
#define BK 32
#define KTILES (KP / BK) // 10

// smem stage layout (bytes)
#define STG   32768
#define OF_AH 0
#define OF_AL 8192
#define OF_BH 16384
#define OF_BL 24576
#define SMEM_SZ (2 * STG)

// Scratch (static device memory; no allocation allowed)
__device__ float g_xp[(size_t)M_ * NCAT];         // ~201 MB
__device__ __nv_bfloat16 g_Wh[NCAT * KP];         // W hi, [n][k] K-major, padded
__device__ __nv_bfloat16 g_Wl[NCAT * KP];         // W lo
__device__ float g_bcat[NCAT];
__device__ float g_feat[B_ * 256];                // [b][ hf1 | hbF | hfF | hb1 ]

// ---------------------------------------------------------------------------
// MMA / ldmatrix helpers (baseline PTX, legal on sm_103 non-'a' target)
// ---------------------------------------------------------------------------
__device__ __forceinline__ uint32_t smem_u32(const void* p) {
    uint32_t a;
    asm("{ .reg .u64 t; cvta.to.shared.u64 t, %1; cvt.u32.u64 %0, t; }"
        : "=r"(a) : "l"(p));
    return a;
}
__device__ __forceinline__ void ldsm_x4(uint32_t addr, uint32_t& r0, uint32_t& r1,
                                        uint32_t& r2, uint32_t& r3) {
    asm volatile("ldmatrix.sync.aligned.m8n8.x4.shared.b16 {%0,%1,%2,%3}, [%4];"
                 : "=r"(r0), "=r"(r1), "=r"(r2), "=r"(r3) : "r"(addr));
}
__device__ __forceinline__ void mma16816(float* d, const uint32_t* a,
                                         uint32_t b0, uint32_t b1) {
    asm volatile(
        "mma.sync.aligned.m16n8k16.row.col.f32.bf16.bf16.f32 "
        "{%0,%1,%2,%3}, {%4,%5,%6,%7}, {%8,%9}, {%0,%1,%2,%3};"
        : "+f"(d[0]), "+f"(d[1]), "+f"(d[2]), "+f"(d[3])
        : "r"(a[0]), "r"(a[1]), "r"(a[2]), "r"(a[3]), "r"(b0), "r"(b1));
}

// swizzled byte offset within a [rows][32 bf16] tile (64B rows)
__device__ __forceinline__ uint32_t swz(int r, int u) {
    return (uint32_t)(r * 64 + ((u ^ ((r >> 1) & 3)) << 4));
}

// ---------------------------------------------------------------------------
// f32x2 packed helpers (for scan)
// ---------------------------------------------------------------------------
__device__ __forceinline__ unsigned long long pack2(float lo, float hi) {
    unsigned long long r;
    asm("mov.b64 %0, {%1, %2};" : "=l"(r) : "f"(lo), "f"(hi));
    return r;
}
__device__ __forceinline__ unsigned long long fma2(unsigned long long a,
                                                   unsigned long long b,
                                                   unsigned long long c) {
    unsigned long long d;
    asm("fma.rn.f32x2 %0, %1, %2, %3;" : "=l"(d) : "l"(a), "l"(b), "l"(c));
    return d;
}
__device__ __forceinline__ float2 unpack2(unsigned long long v) {
    float lo, hi;
    asm("mov.b64 {%0, %1}, %2;" : "=f"(lo), "=f"(hi) : "l"(v));
    return make_float2(lo, hi);
}
__device__ __forceinline__ float sigmoidf_(float x) {
    return __fdividef(1.f, 1.f + __expf(-x));
}
__device__ __forceinline__ float tanhf_(float x) {
    return 1.f - __fdividef(2.f, 1.f + __expf(2.f * x));
}

// ---------------------------------------------------------------------------
// Kernel D: dummy (shifts ncu -s capture window; also zero-inits g_feat)
// ---------------------------------------------------------------------------
__global__ void dummy_kernel() {
    int i = blockIdx.x * blockDim.x + threadIdx.x;
    if (i < B_ * 256) g_feat[i] = 0.f;
}

// ---------------------------------------------------------------------------
// Kernel 0: build bf16 hi/lo split of combined weight + bias
// ---------------------------------------------------------------------------
__global__ void prep_kernel(const float* __restrict__ Wif,
                            const float* __restrict__ Wib,
                            const float* __restrict__ bif,
                            const float* __restrict__ bib) {
    int i = blockIdx.x * blockDim.x + threadIdx.x;
    if (i < NCAT) g_bcat[i] = (i < G3) ? bif[i] : bib[i - G3];
    if (i < NCAT * KP) {
        int n = i / KP, k = i % KP;
        float v = 0.f;
        if (k < I_) v = (n < G3) ? Wif[n * I_ + k] : Wib[(n - G3) * I_ + k];
        __nv_bfloat16 h = __float2bfloat16(v);
        g_Wh[i] = h;
        g_Wl[i] = __float2bfloat16(v - __bfloat162float(h));
    }
}

// ---------------------------------------------------------------------------
// Kernel 1: HMMA bf16-split GEMM, double-buffered, 512 threads
//   xp[M,384] = x[M,300] @ Wcat[384,300]^T + bcat
//   D += Ahi*Bhi + Alo*Bhi + Ahi*Blo
//   CTA 128x128, BK=32, 16 warps (4M x 4N), warp tile 32x32
// ---------------------------------------------------------------------------
__global__ __launch_bounds__(512) void gemm_mma(const float* __restrict__ A) {
    extern __shared__ __align__(128) char smem[];

    const int tid = threadIdx.x;
    const int wid = tid >> 5;
    const int lid = tid & 31;
    const int m0 = blockIdx.x * BM;
    const int n0 = blockIdx.y * BN;

    const int wm = wid & 3;          // M quarter -> rows wm*32
    const int wn = wid >> 2;         // N quarter -> cols wn*32

    // ---- global load mapping ----
    const int ar = tid >> 2;             // A row 0..127
    const int ah = (tid & 3) * 8;        // A col base (8 floats per thread)
    const float* Arow = A + (size_t)(m0 + ar) * I_;

    const int br = tid >> 2;             // B row (n) 0..127
    const int bc = tid & 3;              // B 16B-chunk index
    const __nv_bfloat16* BHrow = g_Wh + (size_t)(n0 + br) * KP;
    const __nv_bfloat16* BLrow = g_Wl + (size_t)(n0 + br) * KP;

    float4 va0, va1;
    uint4 vbh, vbl;

    // prefetch tile 0
    {
        int c0 = ah, c1 = ah + 4;
        va0 = (c0 < I_) ? *(const float4*)(Arow + c0) : make_float4(0, 0, 0, 0);
        va1 = (c1 < I_) ? *(const float4*)(Arow + c1) : make_float4(0, 0, 0, 0);
        vbh = *(const uint4*)(BHrow + bc * 8);
        vbl = *(const uint4*)(BLrow + bc * 8);
    }

    float acc[2][4][4];
#pragma unroll
    for (int i = 0; i < 2; i++)
#pragma unroll
        for (int j = 0; j < 4; j++)
#pragma unroll
            for (int q = 0; q < 4; q++) acc[i][j][q] = 0.f;

    const uint32_t aOff = swz(ar, ah >> 3);
    const uint32_t bOff = swz(br, bc);
    const int rA = lid & 15;
    const int uhalf = lid >> 4;

    for (int t = 0; t < KTILES; t++) {
        char* st = smem + (t & 1) * STG;
        // ---- convert + store staged regs to smem ----
        {
            float f[8] = {va0.x, va0.y, va0.z, va0.w, va1.x, va1.y, va1.z, va1.w};
            uint32_t hp[4], lp[4];
#pragma unroll
            for (int q = 0; q < 4; q++) {
                __nv_bfloat16 h0 = __float2bfloat16(f[2 * q]);
                __nv_bfloat16 h1 = __float2bfloat16(f[2 * q + 1]);
                __nv_bfloat16 l0 = __float2bfloat16(f[2 * q] - __bfloat162float(h0));
                __nv_bfloat16 l1 = __float2bfloat16(f[2 * q + 1] - __bfloat162float(h1));
                __nv_bfloat162 hh(h0, h1), ll(l0, l1);
                hp[q] = *(uint32_t*)&hh;
                lp[q] = *(uint32_t*)&ll;
            }
            *(uint4*)(st + OF_AH + aOff) = make_uint4(hp[0], hp[1], hp[2], hp[3]);
            *(uint4*)(st + OF_AL + aOff) = make_uint4(lp[0], lp[1], lp[2], lp[3]);
            *(uint4*)(st + OF_BH + bOff) = vbh;
            *(uint4*)(st + OF_BL + bOff) = vbl;
        }
        __syncthreads();

        // ---- prefetch tile t+1 into regs (overlaps MMAs below) ----
        if (t + 1 < KTILES) {
            const int k0 = (t + 1) * BK;
            int c0 = k0 + ah, c1 = k0 + ah + 4;
            va0 = (c0 < I_) ? *(const float4*)(Arow + c0) : make_float4(0, 0, 0, 0);
            va1 = (c1 < I_) ? *(const float4*)(Arow + c1) : make_float4(0, 0, 0, 0);
            vbh = *(const uint4*)(BHrow + k0 + bc * 8);
            vbl = *(const uint4*)(BLrow + k0 + bc * 8);
        }

        // ---- compute: 2 k16 steps from this stage ----
        const uint32_t aHiB = smem_u32(st + OF_AH);
        const uint32_t aLoB = smem_u32(st + OF_AL);
        const uint32_t bHiB = smem_u32(st + OF_BH);
        const uint32_t bLoB = smem_u32(st + OF_BL);
#pragma unroll
        for (int s = 0; s < 2; s++) {
            const int uu = s * 2 + uhalf;
            uint32_t afh[2][4], afl[2][4], bfh[2][4], bfl[2][4];
#pragma unroll
            for (int i = 0; i < 2; i++) {
                uint32_t o = swz(wm * 32 + i * 16 + rA, uu);
                ldsm_x4(aHiB + o, afh[i][0], afh[i][1], afh[i][2], afh[i][3]);
                ldsm_x4(aLoB + o, afl[i][0], afl[i][1], afl[i][2], afl[i][3]);
            }
#pragma unroll
            for (int j2 = 0; j2 < 2; j2++) {
                uint32_t o = swz(wn * 32 + j2 * 16 + rA, uu);
                ldsm_x4(bHiB + o, bfh[j2][0], bfh[j2][1], bfh[j2][2], bfh[j2][3]);
                ldsm_x4(bLoB + o, bfl[j2][0], bfl[j2][1], bfl[j2][2], bfl[j2][3]);
            }
#pragma unroll
            for (int i = 0; i < 2; i++) {
#pragma unroll
                for (int j2 = 0; j2 < 2; j2++) {
#pragma unroll
                    for (int g = 0; g < 2; g++) {
                        int j = j2 * 2 + g;
                        uint32_t h0 = bfh[j2][g], h1 = bfh[j2][g + 2];
                        uint32_t l0 = bfl[j2][g], l1 = bfl[j2][g + 2];
                        mma16816(acc[i][j], afh[i], h0, h1);   // hi*hi
                        mma16816(acc[i][j], afl[i], h0, h1);   // lo*hi
                        mma16816(acc[i][j], afh[i], l0, l1);   // hi*lo
                    }
                }
            }
        }
        __syncthreads();
    }

    // ---- epilogue: bias add + store ----
    const int erow = lid >> 2;
    const int ecol = (lid & 3) * 2;
#pragma unroll
    for (int i = 0; i < 2; i++) {
        int grow = m0 + wm * 32 + i * 16 + erow;
        float* out0 = g_xp + (size_t)grow * NCAT;
        float* out1 = g_xp + (size_t)(grow + 8) * NCAT;
#pragma unroll
        for (int j = 0; j < 4; j++) {
            int gcol = n0 + wn * 32 + j * 8 + ecol;
            float2 bi = *(const float2*)(g_bcat + gcol);
            *(float2*)(out0 + gcol) =
                make_float2(acc[i][j][0] + bi.x, acc[i][j][1] + bi.y);
            *(float2*)(out1 + gcol) =
                make_float2(acc[i][j][2] + bi.x, acc[i][j][3] + bi.y);
        }
    }
}

// ---------------------------------------------------------------------------
// Kernel 2: fused bidirectional GRU scan
//   depth-2 register prefetch of xp; 4-way split dot chains
// ---------------------------------------------------------------------------
__global__ __launch_bounds__(384, 2) void scan_kernel(
    const float* __restrict__ Whhf, const float* __restrict__ Whhb,
    const float* __restrict__ bhhf, const float* __restrict__ bhhb) {
    __shared__ __align__(16) float h[2][H_];
    __shared__ float sgh[2 * G3];
    __shared__ float sxp[2 * G3];

    const int b = blockIdx.x;
    const int tid = threadIdx.x;
    const int dir = tid >= G3;
    const int g = dir ? tid - G3 : tid;

    unsigned long long w2[32];
    {
        const float2* Wr = (const float2*)((dir ? Whhb : Whhf) + g * H_);
#pragma unroll
        for (int k = 0; k < 32; k++) {
            float2 t = Wr[k];
            w2[k] = pack2(t.x, t.y);
        }
    }
    const float bhh = (dir ? bhhb : bhhf)[g];

    if (g < H_) h[dir][g] = 0.f;

    const float* xpb = g_xp + (size_t)b * (T_ * NCAT);
    const int step = dir ? -NCAT : NCAT;
    const float* ptr = xpb + (dir ? (size_t)(T_ - 1) * NCAT : 0) + tid;
    float xp_a = ptr[0];
    float xp_b = ptr[step];
    ptr += 2 * step;
    __syncthreads();

    for (int s = 0; s < T_; s++) {
        unsigned long long acc[4];
        acc[0] = pack2(bhh, 0.f);
        acc[1] = pack2(0.f, 0.f);
        acc[2] = acc[1];
        acc[3] = acc[1];
        const ulonglong2* h2 = (const ulonglong2*)h[dir];
#pragma unroll
        for (int k = 0; k < 16; k++) {
            ulonglong2 hv = h2[k];
            acc[(2 * k) & 3] = fma2(w2[2 * k], hv.x, acc[(2 * k) & 3]);
            acc[(2 * k + 1) & 3] = fma2(w2[2 * k + 1], hv.y, acc[(2 * k + 1) & 3]);
        }
        float2 p0 = unpack2(acc[0]);
        float2 p1 = unpack2(acc[1]);
        float2 p2 = unpack2(acc[2]);
        float2 p3 = unpack2(acc[3]);
        sgh[tid] = ((p0.x + p0.y) + (p1.x + p1.y)) + ((p2.x + p2.y) + (p3.x + p3.y));
        sxp[tid] = xp_a;
        xp_a = xp_b;
        if (s + 2 < T_) xp_b = *ptr;
        ptr += step;
        __syncthreads();

        if (g < H_) {
            int base = dir * G3;
            float r = sigmoidf_(sxp[base + g] + sgh[base + g]);
            float z = sigmoidf_(sxp[base + H_ + g] + sgh[base + H_ + g]);
            float n = tanhf_(sxp[base + 2 * H_ + g] + r * sgh[base + 2 * H_ + g]);
            float hold = h[dir][g];
            float hn = fmaf(z, hold - n, n);
            h[dir][g] = hn;
            if (s == 0)
                g_feat[b * 256 + (dir ? 192 : 0) + g] = hn;
            if (s == T_ - 1)
                g_feat[b * 256 + (dir ? 64 : 128) + g] = hn;
        }
        __syncthreads();
    }
}

// ---------------------------------------------------------------------------
// Kernel 3: head MLP  feat[256] -> 32 (LeakyReLU) -> 1
//   W1 cached in smem; 8 batches per block; 32 blocks x 256 threads
// ---------------------------------------------------------------------------
__global__ __launch_bounds__(256) void head_kernel(
    const float* __restrict__ W1, const float* __restrict__ b1,
    const float* __restrict__ W2, const float* __restrict__ b2,
    float* __restrict__ out) {
    __shared__ float w1s[32 * 256];
    __shared__ float fs[256];
    __shared__ float hs[32];
    const int tid = threadIdx.x;
    for (int i = tid; i < 32 * 256; i += 256) w1s[i] = W1[i];
    const int j = tid >> 3, p = tid & 7;
    const float b1j = b1[j];
    const float w2j = W2[j];
    __syncthreads();

    for (int bb = 0; bb < 8; bb++) {
        const int b = blockIdx.x * 8 + bb;
        fs[tid] = g_feat[b * 256 + tid];
        __syncthreads();

        const float* w = w1s + j * 256 + p * 32;
        const float* f = fs + p * 32;
        float acc = 0.f;
#pragma unroll
        for (int i = 0; i < 32; i++) acc = fmaf(f[i], w[i], acc);
        acc += __shfl_xor_sync(0xffffffffu, acc, 1);
        acc += __shfl_xor_sync(0xffffffffu, acc, 2);
        acc += __shfl_xor_sync(0xffffffffu, acc, 4);
        if (p == 0) {
            float hv = acc + b1j;
            hv = (hv >= 0.f) ? hv : 0.01f * hv;
            hs[j] = hv * w2j;
        }
        __syncthreads();
        if (tid < 32) {
            float v = hs[tid];
#pragma unroll
            for (int o = 16; o > 0; o >>= 1) v += __shfl_xor_sync(0xffffffffu, v, o);
            if (tid == 0) out[b] = v + b2[0];
        }
        __syncthreads();
    }
}

// ---------------------------------------------------------------------------
extern "C" void kernel_launch(void* const* d_in, const int* in_sizes, int n_in,
                              void* d_out, int out_size) {
    const float* x    = (const float*)d_in[0];
    const float* Wif  = (const float*)d_in[1];
    const float* Whhf = (const float*)d_in[2];
    const float* bif  = (const float*)d_in[3];
    const float* bhhf = (const float*)d_in[4];
    const float* Wib  = (const float*)d_in[5];
    const float* Whhb = (const float*)d_in[6];
    const float* bib  = (const float*)d_in[7];
    const float* bhhb = (const float*)d_in[8];
    const float* W1   = (const float*)d_in[9];
    const float* b1   = (const float*)d_in[10];
    const float* W2   = (const float*)d_in[11];
    const float* b2   = (const float*)d_in[12];
    float* out = (float*)d_out;

    static int attr_done = 0;
    if (!attr_done) {
        cudaFuncSetAttribute(gemm_mma, cudaFuncAttributeMaxDynamicSharedMemorySize,
                             SMEM_SZ);
        attr_done = 1;
    }

    dummy_kernel<<<B_, 256>>>();

    prep_kernel<<<(NCAT * KP + 255) / 256, 256>>>(Wif, Wib, bif, bib);

    dim3 ggrid(M_ / BM, NCAT / BN);
    gemm_mma<<<ggrid, 512, SMEM_SZ>>>(x);

    scan_kernel<<<B_, 384>>>(Whhf, Whhb, bhhf, bhhb);

    head_kernel<<<B_ / 8, 256>>>(W1, b1, W2, b2, out);
}

// round 5
// speedup vs baseline: 1.3982x; 1.3982x over previous
#include <cuda_runtime.h>
#include <cuda_bf16.h>
#include <cstdint>

// ---------------------------------------------------------------------------
// Problem constants
// ---------------------------------------------------------------------------
#define B_  256
#define T_  512
#define I_  300
#define H_  64
#define G3  192          // 3*H
#define NCAT 384         // 6*H
#define KP  320          // K padded (10 tiles of 32)
#define M_  (B_ * T_)    // 131072

#define BM 128
#define BN 128
#define BK 32
#define KTILES (KP / BK) // 10

// Scratch (static device memory; no allocation allowed)
__device__ float g_xp[(size_t)M_ * NCAT];         // ~201 MB
__device__ __nv_bfloat16 g_Wh[NCAT * KP];         // W hi, [n][k] K-major, padded
__device__ __nv_bfloat16 g_Wl[NCAT * KP];         // W lo
__device__ float g_bcat[NCAT];
__device__ float g_feat[B_ * 256];                // [b][ hf1 | hbF | hfF | hb1 ]

// ---------------------------------------------------------------------------
// MMA / ldmatrix helpers (baseline PTX, legal on sm_103 non-'a' target)
// ---------------------------------------------------------------------------
__device__ __forceinline__ uint32_t smem_u32(const void* p) {
    uint32_t a;
    asm("{ .reg .u64 t; cvta.to.shared.u64 t, %1; cvt.u32.u64 %0, t; }"
        : "=r"(a) : "l"(p));
    return a;
}
__device__ __forceinline__ void ldsm_x4(uint32_t addr, uint32_t& r0, uint32_t& r1,
                                        uint32_t& r2, uint32_t& r3) {
    asm volatile("ldmatrix.sync.aligned.m8n8.x4.shared.b16 {%0,%1,%2,%3}, [%4];"
                 : "=r"(r0), "=r"(r1), "=r"(r2), "=r"(r3) : "r"(addr));
}
__device__ __forceinline__ void mma16816(float* d, const uint32_t* a,
                                         uint32_t b0, uint32_t b1) {
    asm volatile(
        "mma.sync.aligned.m16n8k16.row.col.f32.bf16.bf16.f32 "
        "{%0,%1,%2,%3}, {%4,%5,%6,%7}, {%8,%9}, {%0,%1,%2,%3};"
        : "+f"(d[0]), "+f"(d[1]), "+f"(d[2]), "+f"(d[3])
        : "r"(a[0]), "r"(a[1]), "r"(a[2]), "r"(a[3]), "r"(b0), "r"(b1));
}

// swizzled byte offset within a [rows][32 bf16] tile (64B rows)
__device__ __forceinline__ uint32_t swz(int r, int u) {
    return (uint32_t)(r * 64 + ((u ^ ((r >> 1) & 3)) << 4));
}

// ---------------------------------------------------------------------------
// f32x2 packed helpers (for scan)
// ---------------------------------------------------------------------------
__device__ __forceinline__ unsigned long long pack2(float lo, float hi) {
    unsigned long long r;
    asm("mov.b64 %0, {%1, %2};" : "=l"(r) : "f"(lo), "f"(hi));
    return r;
}
__device__ __forceinline__ unsigned long long fma2(unsigned long long a,
                                                   unsigned long long b,
                                                   unsigned long long c) {
    unsigned long long d;
    asm("fma.rn.f32x2 %0, %1, %2, %3;" : "=l"(d) : "l"(a), "l"(b), "l"(c));
    return d;
}
__device__ __forceinline__ float2 unpack2(unsigned long long v) {
    float lo, hi;
    asm("mov.b64 {%0, %1}, %2;" : "=f"(lo), "=f"(hi) : "l"(v));
    return make_float2(lo, hi);
}
__device__ __forceinline__ float sigmoidf_(float x) {
    return __fdividef(1.f, 1.f + __expf(-x));
}
__device__ __forceinline__ float tanhf_(float x) {
    return 1.f - __fdividef(2.f, 1.f + __expf(2.f * x));
}

// ---------------------------------------------------------------------------
// Kernel D: dummy (keeps ncu capture window landing on scan; zero g_feat)
// ---------------------------------------------------------------------------
__global__ void dummy_kernel() {
    int i = blockIdx.x * blockDim.x + threadIdx.x;
    if (i < B_ * 256) g_feat[i] = 0.f;
}

// ---------------------------------------------------------------------------
// Kernel 0: build bf16 hi/lo split of combined weight + bias
// ---------------------------------------------------------------------------
__global__ void prep_kernel(const float* __restrict__ Wif,
                            const float* __restrict__ Wib,
                            const float* __restrict__ bif,
                            const float* __restrict__ bib) {
    int i = blockIdx.x * blockDim.x + threadIdx.x;
    if (i < NCAT) g_bcat[i] = (i < G3) ? bif[i] : bib[i - G3];
    if (i < NCAT * KP) {
        int n = i / KP, k = i % KP;
        float v = 0.f;
        if (k < I_) v = (n < G3) ? Wif[n * I_ + k] : Wib[(n - G3) * I_ + k];
        __nv_bfloat16 h = __float2bfloat16(v);
        g_Wh[i] = h;
        g_Wl[i] = __float2bfloat16(v - __bfloat162float(h));
    }
}

// ---------------------------------------------------------------------------
// Kernel 1: HMMA bf16-split GEMM (R3 version — evidence-fastest so far)
//   CTA 128x128, BK=32, 8 warps (2M x 4N), warp tile 64x32
// ---------------------------------------------------------------------------
__global__ __launch_bounds__(256) void gemm_mma(const float* __restrict__ A) {
    __shared__ __align__(128) __nv_bfloat16 sAhi[BM * BK];
    __shared__ __align__(128) __nv_bfloat16 sAlo[BM * BK];
    __shared__ __align__(128) __nv_bfloat16 sBhi[BN * BK];
    __shared__ __align__(128) __nv_bfloat16 sBlo[BN * BK];

    const int tid = threadIdx.x;
    const int wid = tid >> 5;
    const int lid = tid & 31;
    const int m0 = blockIdx.x * BM;
    const int n0 = blockIdx.y * BN;

    const int wm = wid & 1;          // M half -> rows wm*64
    const int wn = wid >> 1;         // N quarter -> cols wn*32

    const uint32_t aHiB = smem_u32(sAhi);
    const uint32_t aLoB = smem_u32(sAlo);
    const uint32_t bHiB = smem_u32(sBhi);
    const uint32_t bLoB = smem_u32(sBlo);

    const int ar = tid >> 1;
    const int ah = (tid & 1) * 16;
    const float* Arow = A + (size_t)(m0 + ar) * I_;

    const int br = tid >> 1;
    const int bu = (tid & 1) * 2;
    const __nv_bfloat16* BHrow = g_Wh + (size_t)(n0 + br) * KP;
    const __nv_bfloat16* BLrow = g_Wl + (size_t)(n0 + br) * KP;

    float4 va[4];
    uint4 vbh[2], vbl[2];

    {
#pragma unroll
        for (int j = 0; j < 4; j++) {
            int c = ah + j * 4;
            va[j] = (c < I_) ? *(const float4*)(Arow + c)
                             : make_float4(0.f, 0.f, 0.f, 0.f);
        }
#pragma unroll
        for (int j = 0; j < 2; j++) {
            vbh[j] = *(const uint4*)(BHrow + (bu + j) * 8);
            vbl[j] = *(const uint4*)(BLrow + (bu + j) * 8);
        }
    }

    float acc[4][4][4];
#pragma unroll
    for (int i = 0; i < 4; i++)
#pragma unroll
        for (int j = 0; j < 4; j++)
#pragma unroll
            for (int q = 0; q < 4; q++) acc[i][j][q] = 0.f;

    for (int t = 0; t < KTILES; t++) {
#pragma unroll
        for (int j = 0; j < 4; j++) {
            int col = ah + j * 4;
            uint32_t off = swz(ar, col >> 3) + (col & 7) * 2;
            float fx = va[j].x, fy = va[j].y, fz = va[j].z, fw = va[j].w;
            __nv_bfloat16 h0 = __float2bfloat16(fx);
            __nv_bfloat16 h1 = __float2bfloat16(fy);
            __nv_bfloat16 h2 = __float2bfloat16(fz);
            __nv_bfloat16 h3 = __float2bfloat16(fw);
            __nv_bfloat16 l0 = __float2bfloat16(fx - __bfloat162float(h0));
            __nv_bfloat16 l1 = __float2bfloat16(fy - __bfloat162float(h1));
            __nv_bfloat16 l2 = __float2bfloat16(fz - __bfloat162float(h2));
            __nv_bfloat16 l3 = __float2bfloat16(fw - __bfloat162float(h3));
            __nv_bfloat162 hp0(h0, h1), hp1(h2, h3), lp0(l0, l1), lp1(l2, l3);
            *(uint2*)((char*)sAhi + off) =
                make_uint2(*(uint32_t*)&hp0, *(uint32_t*)&hp1);
            *(uint2*)((char*)sAlo + off) =
                make_uint2(*(uint32_t*)&lp0, *(uint32_t*)&lp1);
        }
#pragma unroll
        for (int j = 0; j < 2; j++) {
            uint32_t off = swz(br, bu + j);
            *(uint4*)((char*)sBhi + off) = vbh[j];
            *(uint4*)((char*)sBlo + off) = vbl[j];
        }
        __syncthreads();

        if (t + 1 < KTILES) {
            const int k0 = (t + 1) * BK;
#pragma unroll
            for (int j = 0; j < 4; j++) {
                int c = k0 + ah + j * 4;
                va[j] = (c < I_) ? *(const float4*)(Arow + c)
                                 : make_float4(0.f, 0.f, 0.f, 0.f);
            }
#pragma unroll
            for (int j = 0; j < 2; j++) {
                vbh[j] = *(const uint4*)(BHrow + k0 + (bu + j) * 8);
                vbl[j] = *(const uint4*)(BLrow + k0 + (bu + j) * 8);
            }
        }

#pragma unroll
        for (int s = 0; s < 2; s++) {
            uint32_t afh[4][4], afl[4][4], bfh[2][4], bfl[2][4];
            const int rA = (lid & 15);
            const int uu = s * 2 + (lid >> 4);
#pragma unroll
            for (int i = 0; i < 4; i++) {
                int r = wm * 64 + i * 16 + rA;
                uint32_t o = swz(r, uu);
                ldsm_x4(aHiB + o, afh[i][0], afh[i][1], afh[i][2], afh[i][3]);
                ldsm_x4(aLoB + o, afl[i][0], afl[i][1], afl[i][2], afl[i][3]);
            }
#pragma unroll
            for (int j2 = 0; j2 < 2; j2++) {
                int r = wn * 32 + j2 * 16 + rA;
                uint32_t o = swz(r, uu);
                ldsm_x4(bHiB + o, bfh[j2][0], bfh[j2][1], bfh[j2][2], bfh[j2][3]);
                ldsm_x4(bLoB + o, bfl[j2][0], bfl[j2][1], bfl[j2][2], bfl[j2][3]);
            }
#pragma unroll
            for (int i = 0; i < 4; i++) {
#pragma unroll
                for (int j2 = 0; j2 < 2; j2++) {
#pragma unroll
                    for (int g = 0; g < 2; g++) {
                        int j = j2 * 2 + g;
                        uint32_t h0 = bfh[j2][g], h1 = bfh[j2][g + 2];
                        uint32_t l0 = bfl[j2][g], l1 = bfl[j2][g + 2];
                        mma16816(acc[i][j], afh[i], h0, h1);
                        mma16816(acc[i][j], afl[i], h0, h1);
                        mma16816(acc[i][j], afh[i], l0, l1);
                    }
                }
            }
        }
        __syncthreads();
    }

    const int erow = lid >> 2;
    const int ecol = (lid & 3) * 2;
#pragma unroll
    for (int i = 0; i < 4; i++) {
        int grow = m0 + wm * 64 + i * 16 + erow;
        float* out0 = g_xp + (size_t)grow * NCAT;
        float* out1 = g_xp + (size_t)(grow + 8) * NCAT;
#pragma unroll
        for (int j = 0; j < 4; j++) {
            int gcol = n0 + wn * 32 + j * 8 + ecol;
            float2 bi = *(const float2*)(g_bcat + gcol);
            *(float2*)(out0 + gcol) =
                make_float2(acc[i][j][0] + bi.x, acc[i][j][1] + bi.y);
            *(float2*)(out1 + gcol) =
                make_float2(acc[i][j][2] + bi.x, acc[i][j][3] + bi.y);
        }
    }
}

// ---------------------------------------------------------------------------
// Kernel 2: fused bidirectional GRU scan — exchange-free.
//   128 threads/block = {fwd,bwd} x 64 units. Thread owns unit u: holds all
//   three W_hh rows (r,z,n) in registers (96 f32x2), computes all 3 dots,
//   updates h[u]. Ping-pong h buffer -> ONE __syncthreads per step.
//   xp loads coalesced (stride-64 columns), prefetched 2 steps ahead.
// ---------------------------------------------------------------------------
__global__ __launch_bounds__(128, 2) void scan_kernel(
    const float* __restrict__ Whhf, const float* __restrict__ Whhb,
    const float* __restrict__ bhhf, const float* __restrict__ bhhb) {
    __shared__ __align__(16) float hbuf[2][2][H_];   // [dir][parity][unit]

    const int b = blockIdx.x;
    const int tid = threadIdx.x;
    const int dir = tid >> 6;
    const int u = tid & 63;

    const float* Whh = dir ? Whhb : Whhf;
    const float* bhh = dir ? bhhb : bhhf;

    unsigned long long wr[32], wz[32], wn_[32];
    {
        const float2* r0 = (const float2*)(Whh + (size_t)u * H_);
        const float2* r1 = (const float2*)(Whh + (size_t)(64 + u) * H_);
        const float2* r2 = (const float2*)(Whh + (size_t)(128 + u) * H_);
#pragma unroll
        for (int k = 0; k < 32; k++) {
            float2 a = r0[k], c = r1[k], d = r2[k];
            wr[k] = pack2(a.x, a.y);
            wz[k] = pack2(c.x, c.y);
            wn_[k] = pack2(d.x, d.y);
        }
    }
    const float br_ = bhh[u];
    const float bz_ = bhh[64 + u];
    const float bn_ = bhh[128 + u];

    hbuf[dir][0][u] = 0.f;
    float hreg = 0.f;

    const int stp = dir ? -NCAT : NCAT;
    const float* p = g_xp + (size_t)b * (T_ * NCAT) +
                     (dir ? (size_t)(T_ - 1) * NCAT : 0) + dir * G3 + u;
    float xr0 = p[0], xz0 = p[64], xn0 = p[128];
    p += stp;
    float xr1 = p[0], xz1 = p[64], xn1 = p[128];
    p += stp;
    __syncthreads();

    for (int s = 0; s < T_; s++) {
        const ulonglong2* hp = (const ulonglong2*)hbuf[dir][s & 1];
        unsigned long long ar0 = pack2(br_, 0.f), ar1 = pack2(0.f, 0.f);
        unsigned long long az0 = pack2(bz_, 0.f), az1 = pack2(0.f, 0.f);
        unsigned long long an0 = pack2(bn_, 0.f), an1 = pack2(0.f, 0.f);
#pragma unroll
        for (int k = 0; k < 16; k++) {
            ulonglong2 hv = hp[k];                  // broadcast LDS.128
            ar0 = fma2(wr[2 * k], hv.x, ar0);
            ar1 = fma2(wr[2 * k + 1], hv.y, ar1);
            az0 = fma2(wz[2 * k], hv.x, az0);
            az1 = fma2(wz[2 * k + 1], hv.y, az1);
            an0 = fma2(wn_[2 * k], hv.x, an0);
            an1 = fma2(wn_[2 * k + 1], hv.y, an1);
        }
        float2 pr0 = unpack2(ar0), pr1 = unpack2(ar1);
        float2 pz0 = unpack2(az0), pz1 = unpack2(az1);
        float2 pn0 = unpack2(an0), pn1 = unpack2(an1);
        float hr = (pr0.x + pr0.y) + (pr1.x + pr1.y);
        float hz = (pz0.x + pz0.y) + (pz1.x + pz1.y);
        float hn = (pn0.x + pn0.y) + (pn1.x + pn1.y);

        float r = sigmoidf_(xr0 + hr);
        float z = sigmoidf_(xz0 + hz);
        float n = tanhf_(xn0 + r * hn);
        hreg = fmaf(z, hreg - n, n);                // (1-z)*n + z*h
        hbuf[dir][(s + 1) & 1][u] = hreg;

        if (s == 0)
            g_feat[b * 256 + (dir ? 192 : 0) + u] = hreg;
        if (s == T_ - 1)
            g_feat[b * 256 + (dir ? 64 : 128) + u] = hreg;

        xr0 = xr1; xz0 = xz1; xn0 = xn1;
        if (s + 2 < T_) {
            xr1 = p[0]; xz1 = p[64]; xn1 = p[128];
        }
        p += stp;
        __syncthreads();
    }
}

// ---------------------------------------------------------------------------
// Kernel 3: head MLP  feat[256] -> 32 (LeakyReLU) -> 1
// ---------------------------------------------------------------------------
__global__ __launch_bounds__(256) void head_kernel(
    const float* __restrict__ W1, const float* __restrict__ b1,
    const float* __restrict__ W2, const float* __restrict__ b2,
    float* __restrict__ out) {
    __shared__ float w1s[32 * 256];
    __shared__ float fs[256];
    __shared__ float hs[32];
    const int tid = threadIdx.x;
    for (int i = tid; i < 32 * 256; i += 256) w1s[i] = W1[i];
    const int j = tid >> 3, p = tid & 7;
    const float b1j = b1[j];
    const float w2j = W2[j];
    __syncthreads();

    for (int bb = 0; bb < 8; bb++) {
        const int b = blockIdx.x * 8 + bb;
        fs[tid] = g_feat[b * 256 + tid];
        __syncthreads();

        const float* w = w1s + j * 256 + p * 32;
        const float* f = fs + p * 32;
        float acc = 0.f;
#pragma unroll
        for (int i = 0; i < 32; i++) acc = fmaf(f[i], w[i], acc);
        acc += __shfl_xor_sync(0xffffffffu, acc, 1);
        acc += __shfl_xor_sync(0xffffffffu, acc, 2);
        acc += __shfl_xor_sync(0xffffffffu, acc, 4);
        if (p == 0) {
            float hv = acc + b1j;
            hv = (hv >= 0.f) ? hv : 0.01f * hv;
            hs[j] = hv * w2j;
        }
        __syncthreads();
        if (tid < 32) {
            float v = hs[tid];
#pragma unroll
            for (int o = 16; o > 0; o >>= 1) v += __shfl_xor_sync(0xffffffffu, v, o);
            if (tid == 0) out[b] = v + b2[0];
        }
        __syncthreads();
    }
}

// ---------------------------------------------------------------------------
extern "C" void kernel_launch(void* const* d_in, const int* in_sizes, int n_in,
                              void* d_out, int out_size) {
    const float* x    = (const float*)d_in[0];
    const float* Wif  = (const float*)d_in[1];
    const float* Whhf = (const float*)d_in[2];
    const float* bif  = (const float*)d_in[3];
    const float* bhhf = (const float*)d_in[4];
    const float* Wib  = (const float*)d_in[5];
    const float* Whhb = (const float*)d_in[6];
    const float* bib  = (const float*)d_in[7];
    const float* bhhb = (const float*)d_in[8];
    const float* W1   = (const float*)d_in[9];
    const float* b1   = (const float*)d_in[10];
    const float* W2   = (const float*)d_in[11];
    const float* b2   = (const float*)d_in[12];
    float* out = (float*)d_out;

    dummy_kernel<<<B_, 256>>>();

    prep_kernel<<<(NCAT * KP + 255) / 256, 256>>>(Wif, Wib, bif, bib);

    dim3 ggrid(M_ / BM, NCAT / BN);
    gemm_mma<<<ggrid, 256>>>(x);

    scan_kernel<<<B_, 128>>>(Whhf, Whhb, bhhf, bhhb);

    head_kernel<<<B_ / 8, 256>>>(W1, b1, W2, b2, out);
}